// round 5
// baseline (speedup 1.0000x reference)
#include <cuda_runtime.h>
#include <cstdint>

#define NN 2048
#define EMBD 16
#define BB 64
#define CC 64

// Scratch (no cudaMalloc allowed)
static __device__ float g_A[NN * NN];           // adjacency (tf32-rounded)
static __device__ float g_XT[BB * CC * NN];     // X^T [b][c][m], tf32-rounded
static __device__ float g_y1[BB * NN * CC];     // A@X (fp32)
static __device__ float g_y1T[BB * CC * NN];    // y1^T [b][c][m], tf32-rounded
static __device__ float g_y2[BB * NN * CC];     // 2A@y1 - X (fp32)
static __device__ float g_WT[NN * 3 * CC * CC]; // per-node weights TRANSPOSED [n][o][kk], tf32

// ---------------------------------------------------------------------------
__device__ __forceinline__ float tf32r(float x) {
    uint32_t o;
    asm("cvt.rna.tf32.f32 %0, %1;" : "=r"(o) : "f"(x));
    return __uint_as_float(o);
}
__device__ __forceinline__ uint32_t smem_u32(const void* p) {
    uint32_t a;
    asm("{ .reg .u64 t; cvta.to.shared.u64 t, %1; cvt.u32.u64 %0, t; }" : "=r"(a) : "l"(p));
    return a;
}
__device__ __forceinline__ void cp16(uint32_t dst, const void* src) {
    asm volatile("cp.async.cg.shared.global [%0], [%1], 16;" :: "r"(dst), "l"(src));
}
__device__ __forceinline__ void cp_commit() { asm volatile("cp.async.commit_group;"); }
__device__ __forceinline__ void cp_wait1() { asm volatile("cp.async.wait_group 1;" ::: "memory"); }
__device__ __forceinline__ void cp_wait0() { asm volatile("cp.async.wait_group 0;" ::: "memory"); }

__device__ __forceinline__ void mma8(float* d, const uint32_t* a, const uint32_t* b) {
    asm volatile(
        "mma.sync.aligned.m16n8k8.row.col.f32.tf32.tf32.f32 "
        "{%0,%1,%2,%3}, {%4,%5,%6,%7}, {%8,%9}, {%0,%1,%2,%3};"
        : "+f"(d[0]), "+f"(d[1]), "+f"(d[2]), "+f"(d[3])
        : "r"(a[0]), "r"(a[1]), "r"(a[2]), "r"(a[3]), "r"(b[0]), "r"(b[1]));
}
__device__ __forceinline__ void ldsm4(uint32_t* r, uint32_t addr) {
    asm volatile("ldmatrix.sync.aligned.m8n8.x4.shared.b16 {%0,%1,%2,%3}, [%4];"
                 : "=r"(r[0]), "=r"(r[1]), "=r"(r[2]), "=r"(r[3]) : "r"(addr));
}

// ---------------------------------------------------------------------------
// K0: A[row,:] = tf32_round(softmax(relu(E[row] . E[j])))
// ---------------------------------------------------------------------------
__global__ __launch_bounds__(256) void supports_kernel(const float* __restrict__ E,
                                                       float* __restrict__ A) {
    __shared__ float z[NN];
    __shared__ float red[8];
    __shared__ float en[EMBD];
    int row = blockIdx.x;
    int tid = threadIdx.x;
    if (tid < EMBD) en[tid] = E[row * EMBD + tid];
    __syncthreads();
    float er[EMBD];
#pragma unroll
    for (int d = 0; d < EMBD; d++) er[d] = en[d];

    float lmax = 0.f;
    for (int j = tid; j < NN; j += 256) {
        const float4* ej = reinterpret_cast<const float4*>(E + (size_t)j * EMBD);
        float s = 0.f;
#pragma unroll
        for (int q = 0; q < 4; q++) {
            float4 v = ej[q];
            s = fmaf(er[q * 4 + 0], v.x, s);
            s = fmaf(er[q * 4 + 1], v.y, s);
            s = fmaf(er[q * 4 + 2], v.z, s);
            s = fmaf(er[q * 4 + 3], v.w, s);
        }
        s = fmaxf(s, 0.f);
        z[j] = s;
        lmax = fmaxf(lmax, s);
    }
#pragma unroll
    for (int o = 16; o > 0; o >>= 1) lmax = fmaxf(lmax, __shfl_xor_sync(~0u, lmax, o));
    if ((tid & 31) == 0) red[tid >> 5] = lmax;
    __syncthreads();
    float bmax = red[0];
#pragma unroll
    for (int w = 1; w < 8; w++) bmax = fmaxf(bmax, red[w]);
    __syncthreads();

    float lsum = 0.f;
    for (int j = tid; j < NN; j += 256) {
        float e = expf(z[j] - bmax);
        z[j] = e;
        lsum += e;
    }
#pragma unroll
    for (int o = 16; o > 0; o >>= 1) lsum += __shfl_xor_sync(~0u, lsum, o);
    if ((tid & 31) == 0) red[tid >> 5] = lsum;
    __syncthreads();
    float bsum = 0.f;
#pragma unroll
    for (int w = 0; w < 8; w++) bsum += red[w];
    float inv = 1.f / bsum;
    for (int j = tid; j < NN; j += 256) A[(size_t)row * NN + j] = tf32r(z[j] * inv);
}

// ---------------------------------------------------------------------------
// Transpose per b: dst[b][c][m] = tf32_round(src[b][m][c]). 32x32 tiles.
// ---------------------------------------------------------------------------
__global__ __launch_bounds__(256) void tr_kernel(const float* __restrict__ S,
                                                 float* __restrict__ D) {
    __shared__ float Ts[32][33];
    int m0 = blockIdx.x * 32;
    int c0 = blockIdx.y * 32;
    int b = blockIdx.z;
    int tid = threadIdx.x;
    int r = tid >> 3, q = tid & 7;
    float4 v = *reinterpret_cast<const float4*>(S + ((size_t)b * NN + m0 + r) * CC + c0 + q * 4);
    Ts[r][q * 4 + 0] = v.x;
    Ts[r][q * 4 + 1] = v.y;
    Ts[r][q * 4 + 2] = v.z;
    Ts[r][q * 4 + 3] = v.w;
    __syncthreads();
    float4 o;
    o.x = tf32r(Ts[q * 4 + 0][r]);
    o.y = tf32r(Ts[q * 4 + 1][r]);
    o.z = tf32r(Ts[q * 4 + 2][r]);
    o.w = tf32r(Ts[q * 4 + 3][r]);
    *reinterpret_cast<float4*>(D + ((size_t)b * CC + c0 + r) * NN + m0 + q * 4) = o;
}

// ---------------------------------------------------------------------------
// W precompute (transposed): WT[n][o*192 + kk] = tf32(sum_d E[n,d]*wp[d, kk*64+o])
// ---------------------------------------------------------------------------
__global__ __launch_bounds__(256) void wpre_kernel(const float* __restrict__ E,
                                                   const float* __restrict__ wp,
                                                   float* __restrict__ WT) {
    __shared__ float wps[EMBD][256];
    __shared__ float Es[32][EMBD];
    int k0 = blockIdx.x * 4;
    int idx0 = blockIdx.x * 256;
    int n0 = blockIdx.y * 32;
    int tid = threadIdx.x;
#pragma unroll
    for (int i = 0; i < 4; i++) {
        int f = tid + i * 256;
        int d = f >> 6, c4 = f & 63;
        float4 v = *reinterpret_cast<const float4*>(wp + (size_t)d * 12288 + idx0 + c4 * 4);
        *reinterpret_cast<float4*>(&wps[d][c4 * 4]) = v;
    }
    if (tid < 128) {
        int nl = tid >> 2, dq = tid & 3;
        float4 v = *reinterpret_cast<const float4*>(E + (n0 + nl) * EMBD + dq * 4);
        *reinterpret_cast<float4*>(&Es[nl][dq * 4]) = v;
    }
    __syncthreads();

    int o = tid & 63;
    int g = tid >> 6;
    float wc[4][EMBD];
#pragma unroll
    for (int dk = 0; dk < 4; dk++)
#pragma unroll
        for (int d = 0; d < EMBD; d++) wc[dk][d] = wps[d][dk * 64 + o];

#pragma unroll
    for (int q = 0; q < 8; q++) {
        int nl = g * 8 + q;
        float s[4] = {0.f, 0.f, 0.f, 0.f};
#pragma unroll
        for (int d = 0; d < EMBD; d++) {
            float e = Es[nl][d];
#pragma unroll
            for (int dk = 0; dk < 4; dk++) s[dk] = fmaf(e, wc[dk][d], s[dk]);
        }
        float4 v = make_float4(tf32r(s[0]), tf32r(s[1]), tf32r(s[2]), tf32r(s[3]));
        *reinterpret_cast<float4*>(WT + (size_t)(n0 + nl) * 12288 + o * 192 + k0) = v;
    }
}

// ---------------------------------------------------------------------------
// tf32 mma.sync GEMM: CTA 128x128xK32, 4 warps (128 thr), warp tile 64x64.
// ldmatrix fragments, 3-stage cp.async pipeline, 2 CTAs/SM.
// D[n, bc] = sum_m A[n,m] * Bt[bc, m].  mode 1: Y=acc. mode 2: Y=2*acc-Xsub.
// ---------------------------------------------------------------------------
#define SROW 36
#define STAGE_F (128 * SROW)            // floats per operand stage (18432 B)
#define GEMM_SMEM (6 * STAGE_F * 4)     // 3 stages x (A,B) = 110592 B

__global__ __launch_bounds__(128) void mma_gemm(const float* __restrict__ Ag,
                                                const float* __restrict__ Bt,
                                                float* __restrict__ Y,
                                                const float* __restrict__ Xsub,
                                                int mode) {
    extern __shared__ float sm[];
    uint32_t sb = smem_u32(sm);
    uint32_t aBuf[3], bBuf[3];
#pragma unroll
    for (int s = 0; s < 3; s++) {
        aBuf[s] = sb + (2 * s) * STAGE_F * 4;
        bBuf[s] = sb + (2 * s + 1) * STAGE_F * 4;
    }

    int tid = threadIdx.x;
    int wid = tid >> 5;
    int lid = tid & 31;
    int wm = wid & 1;   // m offset *64
    int wn = wid >> 1;  // n offset *64
    int n0 = blockIdx.x * 128;
    int bc0 = blockIdx.y * 128;

    const float* Arow = Ag + (size_t)n0 * NN;
    const float* Brow = Bt + (size_t)bc0 * NN;

    int ldrow = tid >> 3;  // 0..15
    int ldch = tid & 7;    // 0..7

    auto load_tile = [&](int it, int buf) {
        int m0 = it * 32;
#pragma unroll
        for (int i = 0; i < 8; i++) {
            int row = ldrow + i * 16;
            cp16(aBuf[buf] + (row * SROW + ldch * 4) * 4, Arow + (size_t)row * NN + m0 + ldch * 4);
        }
#pragma unroll
        for (int i = 0; i < 8; i++) {
            int row = ldrow + i * 16;
            cp16(bBuf[buf] + (row * SROW + ldch * 4) * 4, Brow + (size_t)row * NN + m0 + ldch * 4);
        }
        cp_commit();
    };

    // ldmatrix lane-relative offsets (bytes)
    int lm = lid >> 3, lrw = lid & 7;
    uint32_t aLaneRel = ((wm * 64 + (lm & 1) * 8 + lrw) * SROW + (lm >> 1) * 4) * 4;
    uint32_t bLaneRel = ((wn * 64 + (lm >> 1) * 8 + lrw) * SROW + (lm & 1) * 4) * 4;

    float acc[4][8][4];
#pragma unroll
    for (int mt = 0; mt < 4; mt++)
#pragma unroll
        for (int nt = 0; nt < 8; nt++)
#pragma unroll
            for (int q = 0; q < 4; q++) acc[mt][nt][q] = 0.f;

    load_tile(0, 0);
    load_tile(1, 1);

    const int ITERS = NN / 32;
    for (int it = 0; it < ITERS; it++) {
        int buf = it % 3;
        if (it == ITERS - 1) cp_wait0(); else cp_wait1();
        __syncthreads();
        uint32_t aB = aBuf[buf] + aLaneRel;
        uint32_t bB = bBuf[buf] + bLaneRel;
#pragma unroll
        for (int ks = 0; ks < 4; ks++) {
            int k0 = ks * 8;
            uint32_t af[4][4];
#pragma unroll
            for (int mt = 0; mt < 4; mt++)
                ldsm4(af[mt], aB + (mt * 16 * SROW + k0) * 4);
            uint32_t bf[4][4];
#pragma unroll
            for (int g = 0; g < 4; g++)
                ldsm4(bf[g], bB + (g * 16 * SROW + k0) * 4);
#pragma unroll
            for (int mt = 0; mt < 4; mt++)
#pragma unroll
                for (int nt = 0; nt < 8; nt++)
                    mma8(acc[mt][nt], af[mt], &bf[nt >> 1][(nt & 1) * 2]);
        }
        if (it + 2 < ITERS) load_tile(it + 2, (it + 2) % 3);
    }

    int lr = lid >> 2, lc = lid & 3;
#pragma unroll
    for (int mt = 0; mt < 4; mt++) {
#pragma unroll
        for (int nt = 0; nt < 8; nt++) {
            int n = n0 + wm * 64 + mt * 16 + lr;
            int bc = bc0 + wn * 64 + nt * 8 + lc * 2;
            int b = bc >> 6, c = bc & 63;
            float2 v0 = make_float2(acc[mt][nt][0], acc[mt][nt][1]);
            float2 v1 = make_float2(acc[mt][nt][2], acc[mt][nt][3]);
            if (mode == 2) {
                const float2 x0 = *reinterpret_cast<const float2*>(
                    Xsub + ((size_t)b * NN + n) * CC + c);
                const float2 x1 = *reinterpret_cast<const float2*>(
                    Xsub + ((size_t)b * NN + n + 8) * CC + c);
                v0.x = fmaf(2.f, v0.x, -x0.x);
                v0.y = fmaf(2.f, v0.y, -x0.y);
                v1.x = fmaf(2.f, v1.x, -x1.x);
                v1.y = fmaf(2.f, v1.y, -x1.y);
            }
            *reinterpret_cast<float2*>(Y + ((size_t)b * NN + n) * CC + c) = v0;
            *reinterpret_cast<float2*>(Y + ((size_t)b * NN + n + 8) * CC + c) = v1;
        }
    }
}

// ---------------------------------------------------------------------------
// out3: per-node tensor-core contraction. One block (128 thr, 4 warps) per n.
//   D[64 b, 64 o] = XG[64 b, 192 kk] @ WT[64 o, 192 kk]^T  + bias
// ---------------------------------------------------------------------------
#define OSTR 196
#define OUT3_SMEM ((64 * OSTR * 2 + 64) * 4)
__global__ __launch_bounds__(128) void out3_kernel(const float* __restrict__ X,
                                                   const float* __restrict__ E,
                                                   const float* __restrict__ WTg,
                                                   const float* __restrict__ bp,
                                                   float* __restrict__ OUT) {
    extern __shared__ float sm[];
    float* XGs = sm;                  // 64 * 196
    float* WTs = sm + 64 * OSTR;      // 64 * 196
    float* bs = sm + 64 * OSTR * 2;   // 64
    __shared__ float en[EMBD];

    int n = blockIdx.x;
    int tid = threadIdx.x;
    int wid = tid >> 5;
    int lid = tid & 31;
    if (tid < EMBD) en[tid] = E[n * EMBD + tid];
    __syncthreads();

    const float* srcs[3] = {X, g_y1, g_y2};
#pragma unroll
    for (int k = 0; k < 3; k++) {
        const float* src = srcs[k];
#pragma unroll
        for (int rep = 0; rep < 32; rep++) {
            int idx = tid + rep * 128;
            int b = idx >> 6, i = idx & 63;
            XGs[b * OSTR + k * 64 + i] = tf32r(src[((size_t)b * NN + n) * CC + i]);
        }
    }
    {
        const float4* src = reinterpret_cast<const float4*>(WTg + (size_t)n * 12288);
#pragma unroll
        for (int rep = 0; rep < 24; rep++) {
            int f4 = tid + rep * 128;
            int idx = f4 * 4;
            int o = idx / 192, kk = idx - o * 192;
            *reinterpret_cast<float4*>(&WTs[o * OSTR + kk]) = src[f4];
        }
    }
    if (tid < 64) {
        float s = 0.f;
#pragma unroll
        for (int d = 0; d < EMBD; d++) s = fmaf(en[d], bp[d * 64 + tid], s);
        bs[tid] = s;
    }
    __syncthreads();

    int lm = lid >> 3, lrw = lid & 7;
    uint32_t aLane = smem_u32(XGs) + ((wid * 16 + (lm & 1) * 8 + lrw) * OSTR + (lm >> 1) * 4) * 4;
    uint32_t bLane = smem_u32(WTs) + (((lm >> 1) * 8 + lrw) * OSTR + (lm & 1) * 4) * 4;

    float acc[8][4];
#pragma unroll
    for (int nt = 0; nt < 8; nt++)
#pragma unroll
        for (int q = 0; q < 4; q++) acc[nt][q] = 0.f;

#pragma unroll 2
    for (int kt = 0; kt < 24; kt++) {
        int k0 = kt * 8;
        uint32_t af[4];
        ldsm4(af, aLane + k0 * 4);
#pragma unroll
        for (int g = 0; g < 4; g++) {
            uint32_t bf[4];
            ldsm4(bf, bLane + (g * 16 * OSTR + k0) * 4);
            mma8(acc[g * 2 + 0], af, &bf[0]);
            mma8(acc[g * 2 + 1], af, &bf[2]);
        }
    }

    int lr = lid >> 2, lc = lid & 3;
    int b0 = wid * 16 + lr;
#pragma unroll
    for (int nt = 0; nt < 8; nt++) {
        int o = nt * 8 + lc * 2;
        float2 bias = *reinterpret_cast<const float2*>(&bs[o]);
        float2 v0 = make_float2(acc[nt][0] + bias.x, acc[nt][1] + bias.y);
        float2 v1 = make_float2(acc[nt][2] + bias.x, acc[nt][3] + bias.y);
        *reinterpret_cast<float2*>(OUT + ((size_t)b0 * NN + n) * CC + o) = v0;
        *reinterpret_cast<float2*>(OUT + ((size_t)(b0 + 8) * NN + n) * CC + o) = v1;
    }
}

// ---------------------------------------------------------------------------
extern "C" void kernel_launch(void* const* d_in, const int* in_sizes, int n_in,
                              void* d_out, int out_size) {
    const float *x = nullptr, *E = nullptr, *wp = nullptr, *bp = nullptr;
    for (int i = 0; i < n_in; i++) {
        switch (in_sizes[i]) {
            case BB * NN * CC:       x = (const float*)d_in[i]; break;
            case NN * EMBD:          E = (const float*)d_in[i]; break;
            case EMBD * 3 * CC * CC: wp = (const float*)d_in[i]; break;
            case EMBD * CC:          bp = (const float*)d_in[i]; break;
        }
    }
    float* out = (float*)d_out;

    float *A, *XT, *y1, *y1T, *y2, *WT;
    cudaGetSymbolAddress((void**)&A, g_A);
    cudaGetSymbolAddress((void**)&XT, g_XT);
    cudaGetSymbolAddress((void**)&y1, g_y1);
    cudaGetSymbolAddress((void**)&y1T, g_y1T);
    cudaGetSymbolAddress((void**)&y2, g_y2);
    cudaGetSymbolAddress((void**)&WT, g_WT);

    supports_kernel<<<NN, 256>>>(E, A);
    tr_kernel<<<dim3(NN / 32, CC / 32, BB), 256>>>(x, XT);
    wpre_kernel<<<dim3(48, 64), 256>>>(E, wp, WT);

    cudaFuncSetAttribute(mma_gemm, cudaFuncAttributeMaxDynamicSharedMemorySize, GEMM_SMEM);
    dim3 ggrid(NN / 128, (BB * CC) / 128);
    mma_gemm<<<ggrid, 128, GEMM_SMEM>>>(A, XT, y1, nullptr, 1);
    tr_kernel<<<dim3(NN / 32, CC / 32, BB), 256>>>(y1, y1T);
    mma_gemm<<<ggrid, 128, GEMM_SMEM>>>(A, y1T, y2, x, 2);

    cudaFuncSetAttribute(out3_kernel, cudaFuncAttributeMaxDynamicSharedMemorySize, OUT3_SMEM);
    out3_kernel<<<NN, 128, OUT3_SMEM>>>(x, E, WT, bp, out);
}

// round 6
// speedup vs baseline: 1.5061x; 1.5061x over previous
#include <cuda_runtime.h>
#include <cuda_fp16.h>
#include <cstdint>

#define NN 2048
#define EMBD 16
#define BB 64
#define CC 64

// Scratch (no cudaMalloc allowed)
static __device__ __half g_A[NN * NN];            // adjacency, fp16
static __device__ __half g_XT[BB * CC * NN];      // X^T [b][c][m], fp16
static __device__ float  g_y1[BB * NN * CC];      // A@X (fp32)
static __device__ __half g_y1T[BB * CC * NN];     // y1^T [b][c][m], fp16
static __device__ float  g_y2[BB * NN * CC];      // 2A@y1 - X (fp32)
static __device__ float  g_WT[NN * 3 * CC * CC];  // per-node weights [n][o][kk], tf32

// ---------------------------------------------------------------------------
__device__ __forceinline__ float tf32r(float x) {
    uint32_t o;
    asm("cvt.rna.tf32.f32 %0, %1;" : "=r"(o) : "f"(x));
    return __uint_as_float(o);
}
__device__ __forceinline__ uint32_t smem_u32(const void* p) {
    uint32_t a;
    asm("{ .reg .u64 t; cvta.to.shared.u64 t, %1; cvt.u32.u64 %0, t; }" : "=r"(a) : "l"(p));
    return a;
}
__device__ __forceinline__ void cp16(uint32_t dst, const void* src) {
    asm volatile("cp.async.cg.shared.global [%0], [%1], 16;" :: "r"(dst), "l"(src));
}
__device__ __forceinline__ void cp_commit() { asm volatile("cp.async.commit_group;"); }
__device__ __forceinline__ void cp_wait2() { asm volatile("cp.async.wait_group 2;" ::: "memory"); }

// fp16 mma: D(f32) += A(f16) * B(f16),  m16n8k16
__device__ __forceinline__ void mma16(float* d, const uint32_t* a, uint32_t b0, uint32_t b1) {
    asm volatile(
        "mma.sync.aligned.m16n8k16.row.col.f32.f16.f16.f32 "
        "{%0,%1,%2,%3}, {%4,%5,%6,%7}, {%8,%9}, {%0,%1,%2,%3};"
        : "+f"(d[0]), "+f"(d[1]), "+f"(d[2]), "+f"(d[3])
        : "r"(a[0]), "r"(a[1]), "r"(a[2]), "r"(a[3]), "r"(b0), "r"(b1));
}
// tf32 mma (used by out3)
__device__ __forceinline__ void mma8(float* d, const uint32_t* a, const uint32_t* b) {
    asm volatile(
        "mma.sync.aligned.m16n8k8.row.col.f32.tf32.tf32.f32 "
        "{%0,%1,%2,%3}, {%4,%5,%6,%7}, {%8,%9}, {%0,%1,%2,%3};"
        : "+f"(d[0]), "+f"(d[1]), "+f"(d[2]), "+f"(d[3])
        : "r"(a[0]), "r"(a[1]), "r"(a[2]), "r"(a[3]), "r"(b[0]), "r"(b[1]));
}
__device__ __forceinline__ void ldsm4(uint32_t* r, uint32_t addr) {
    asm volatile("ldmatrix.sync.aligned.m8n8.x4.shared.b16 {%0,%1,%2,%3}, [%4];"
                 : "=r"(r[0]), "=r"(r[1]), "=r"(r[2]), "=r"(r[3]) : "r"(addr));
}

// ---------------------------------------------------------------------------
// K0: A[row,:] = fp16(softmax(relu(E[row] . E[j])))
// ---------------------------------------------------------------------------
__global__ __launch_bounds__(256) void supports_kernel(const float* __restrict__ E,
                                                       __half* __restrict__ A) {
    __shared__ float z[NN];
    __shared__ float red[8];
    __shared__ float en[EMBD];
    int row = blockIdx.x;
    int tid = threadIdx.x;
    if (tid < EMBD) en[tid] = E[row * EMBD + tid];
    __syncthreads();
    float er[EMBD];
#pragma unroll
    for (int d = 0; d < EMBD; d++) er[d] = en[d];

    float lmax = 0.f;
    for (int j = tid; j < NN; j += 256) {
        const float4* ej = reinterpret_cast<const float4*>(E + (size_t)j * EMBD);
        float s = 0.f;
#pragma unroll
        for (int q = 0; q < 4; q++) {
            float4 v = ej[q];
            s = fmaf(er[q * 4 + 0], v.x, s);
            s = fmaf(er[q * 4 + 1], v.y, s);
            s = fmaf(er[q * 4 + 2], v.z, s);
            s = fmaf(er[q * 4 + 3], v.w, s);
        }
        s = fmaxf(s, 0.f);
        z[j] = s;
        lmax = fmaxf(lmax, s);
    }
#pragma unroll
    for (int o = 16; o > 0; o >>= 1) lmax = fmaxf(lmax, __shfl_xor_sync(~0u, lmax, o));
    if ((tid & 31) == 0) red[tid >> 5] = lmax;
    __syncthreads();
    float bmax = red[0];
#pragma unroll
    for (int w = 1; w < 8; w++) bmax = fmaxf(bmax, red[w]);
    __syncthreads();

    float lsum = 0.f;
    for (int j = tid; j < NN; j += 256) {
        float e = expf(z[j] - bmax);
        z[j] = e;
        lsum += e;
    }
#pragma unroll
    for (int o = 16; o > 0; o >>= 1) lsum += __shfl_xor_sync(~0u, lsum, o);
    if ((tid & 31) == 0) red[tid >> 5] = lsum;
    __syncthreads();
    float bsum = 0.f;
#pragma unroll
    for (int w = 0; w < 8; w++) bsum += red[w];
    float inv = 1.f / bsum;
    for (int j = tid; j < NN; j += 256) A[(size_t)row * NN + j] = __float2half_rn(z[j] * inv);
}

// ---------------------------------------------------------------------------
// Transpose per b: D[b][c][m] = fp16(S[b][m][c]). 32x32 tiles.
// ---------------------------------------------------------------------------
__global__ __launch_bounds__(256) void trh_kernel(const float* __restrict__ S,
                                                  __half* __restrict__ D) {
    __shared__ float Ts[32][33];
    int m0 = blockIdx.x * 32;
    int c0 = blockIdx.y * 32;
    int b = blockIdx.z;
    int tid = threadIdx.x;
    int r = tid >> 3, q = tid & 7;
    float4 v = *reinterpret_cast<const float4*>(S + ((size_t)b * NN + m0 + r) * CC + c0 + q * 4);
    Ts[r][q * 4 + 0] = v.x;
    Ts[r][q * 4 + 1] = v.y;
    Ts[r][q * 4 + 2] = v.z;
    Ts[r][q * 4 + 3] = v.w;
    __syncthreads();
    __half2 p0 = __halves2half2(__float2half_rn(Ts[q * 4 + 0][r]),
                                __float2half_rn(Ts[q * 4 + 1][r]));
    __half2 p1 = __halves2half2(__float2half_rn(Ts[q * 4 + 2][r]),
                                __float2half_rn(Ts[q * 4 + 3][r]));
    __half2* dptr = reinterpret_cast<__half2*>(D + ((size_t)b * CC + c0 + r) * NN + m0 + q * 4);
    dptr[0] = p0;
    dptr[1] = p1;
}

// ---------------------------------------------------------------------------
// W precompute (transposed): WT[n][o*192 + kk] = tf32(sum_d E[n,d]*wp[d, kk*64+o])
// ---------------------------------------------------------------------------
__global__ __launch_bounds__(256) void wpre_kernel(const float* __restrict__ E,
                                                   const float* __restrict__ wp,
                                                   float* __restrict__ WT) {
    __shared__ float wps[EMBD][256];
    __shared__ float Es[32][EMBD];
    int k0 = blockIdx.x * 4;
    int idx0 = blockIdx.x * 256;
    int n0 = blockIdx.y * 32;
    int tid = threadIdx.x;
#pragma unroll
    for (int i = 0; i < 4; i++) {
        int f = tid + i * 256;
        int d = f >> 6, c4 = f & 63;
        float4 v = *reinterpret_cast<const float4*>(wp + (size_t)d * 12288 + idx0 + c4 * 4);
        *reinterpret_cast<float4*>(&wps[d][c4 * 4]) = v;
    }
    if (tid < 128) {
        int nl = tid >> 2, dq = tid & 3;
        float4 v = *reinterpret_cast<const float4*>(E + (n0 + nl) * EMBD + dq * 4);
        *reinterpret_cast<float4*>(&Es[nl][dq * 4]) = v;
    }
    __syncthreads();

    int o = tid & 63;
    int g = tid >> 6;
    float wc[4][EMBD];
#pragma unroll
    for (int dk = 0; dk < 4; dk++)
#pragma unroll
        for (int d = 0; d < EMBD; d++) wc[dk][d] = wps[d][dk * 64 + o];

#pragma unroll
    for (int q = 0; q < 8; q++) {
        int nl = g * 8 + q;
        float s[4] = {0.f, 0.f, 0.f, 0.f};
#pragma unroll
        for (int d = 0; d < EMBD; d++) {
            float e = Es[nl][d];
#pragma unroll
            for (int dk = 0; dk < 4; dk++) s[dk] = fmaf(e, wc[dk][d], s[dk]);
        }
        float4 v = make_float4(tf32r(s[0]), tf32r(s[1]), tf32r(s[2]), tf32r(s[3]));
        *reinterpret_cast<float4*>(WT + (size_t)(n0 + nl) * 12288 + o * 192 + k0) = v;
    }
}

// ---------------------------------------------------------------------------
// fp16 mma.sync GEMM: CTA 128x128xK32, 8 warps (2m x 4n), warp tile 64x32.
// 4-stage cp.async pipeline, fp16 operands (64B rows, XOR swizzle), fp32 acc.
// D[n, bc] = sum_m A[n,m] * Bt[bc, m].  mode 1: Y=acc. mode 2: Y=2*acc-Xsub.
// ---------------------------------------------------------------------------
#define GEMM_SMEM 65536  // 4 stages x (A 8KB + B 8KB)

__global__ __launch_bounds__(256, 2) void mma_gemm(const __half* __restrict__ Ag,
                                                   const __half* __restrict__ Bt,
                                                   float* __restrict__ Y,
                                                   const float* __restrict__ Xsub,
                                                   int mode) {
    extern __shared__ char smc[];
    uint32_t sb = smem_u32(smc);

    int tid = threadIdx.x;
    int wid = tid >> 5;
    int lid = tid & 31;
    int wm = wid & 1;   // m offset *64
    int wn = wid >> 1;  // n offset *32
    int n0 = blockIdx.x * 128;
    int bc0 = blockIdx.y * 128;

    const __half* Arow = Ag + (size_t)n0 * NN;
    const __half* Brow = Bt + (size_t)bc0 * NN;

    // loader: 128 rows x 64B per operand; thread covers 2 (row,chunk) pairs each.
    auto load_tile = [&](int it, int buf) {
        int m0 = it * 32;
        uint32_t ab = sb + buf * 16384;
        uint32_t bb = ab + 8192;
#pragma unroll
        for (int i = 0; i < 2; i++) {
            int idx = tid + i * 256;
            int row = idx >> 2, c = idx & 3;
            int pc = c ^ ((row >> 1) & 3);
            cp16(ab + row * 64 + pc * 16, Arow + (size_t)row * NN + m0 + c * 8);
        }
#pragma unroll
        for (int i = 0; i < 2; i++) {
            int idx = tid + i * 256;
            int row = idx >> 2, c = idx & 3;
            int pc = c ^ ((row >> 1) & 3);
            cp16(bb + row * 64 + pc * 16, Brow + (size_t)row * NN + m0 + c * 8);
        }
        cp_commit();
    };

    int lm = lid >> 3, lrw = lid & 7;
    int xorv = (lrw >> 1) & 3;
    int chHalf = lm >> 1;                               // k-half within k16
    uint32_t aBase = (uint32_t)(wm * 64 + (lm & 1) * 8 + lrw) * 64;  // + mt*1024
    uint32_t bBase = (uint32_t)(wn * 32 + (lm & 1) * 8 + lrw) * 64;  // + g*1024

    float acc[4][4][4];
#pragma unroll
    for (int mt = 0; mt < 4; mt++)
#pragma unroll
        for (int nt = 0; nt < 4; nt++)
#pragma unroll
            for (int q = 0; q < 4; q++) acc[mt][nt][q] = 0.f;

    load_tile(0, 0);
    load_tile(1, 1);
    load_tile(2, 2);

    const int ITERS = NN / 32;
    for (int it = 0; it < ITERS; it++) {
        int buf = it & 3;
        cp_wait2();
        __syncthreads();
        uint32_t aB = sb + buf * 16384 + aBase;
        uint32_t bB = sb + buf * 16384 + 8192 + bBase;

        uint32_t af[4][4], bf[2][4];
        // ks = 0 (k 0..15)
        {
            uint32_t pc = (uint32_t)((0 + chHalf) ^ xorv) * 16;
#pragma unroll
            for (int mt = 0; mt < 4; mt++) ldsm4(af[mt], aB + mt * 1024 + pc);
#pragma unroll
            for (int g = 0; g < 2; g++) ldsm4(bf[g], bB + g * 1024 + pc);
        }
        if (it + 3 < ITERS) load_tile(it + 3, (it + 3) & 3); else cp_commit();
#pragma unroll
        for (int mt = 0; mt < 4; mt++)
#pragma unroll
            for (int g = 0; g < 2; g++) {
                mma16(acc[mt][g * 2 + 0], af[mt], bf[g][0], bf[g][2]);
                mma16(acc[mt][g * 2 + 1], af[mt], bf[g][1], bf[g][3]);
            }
        // ks = 1 (k 16..31)
        {
            uint32_t pc = (uint32_t)((2 + chHalf) ^ xorv) * 16;
#pragma unroll
            for (int mt = 0; mt < 4; mt++) ldsm4(af[mt], aB + mt * 1024 + pc);
#pragma unroll
            for (int g = 0; g < 2; g++) ldsm4(bf[g], bB + g * 1024 + pc);
        }
#pragma unroll
        for (int mt = 0; mt < 4; mt++)
#pragma unroll
            for (int g = 0; g < 2; g++) {
                mma16(acc[mt][g * 2 + 0], af[mt], bf[g][0], bf[g][2]);
                mma16(acc[mt][g * 2 + 1], af[mt], bf[g][1], bf[g][3]);
            }
    }

    int lr = lid >> 2, lc = lid & 3;
#pragma unroll
    for (int mt = 0; mt < 4; mt++) {
#pragma unroll
        for (int nt = 0; nt < 4; nt++) {
            int n = n0 + wm * 64 + mt * 16 + lr;
            int bc = bc0 + wn * 32 + (nt >> 1) * 16 + (nt & 1) * 8 + lc * 2;
            int b = bc >> 6, c = bc & 63;
            float2 v0 = make_float2(acc[mt][nt][0], acc[mt][nt][1]);
            float2 v1 = make_float2(acc[mt][nt][2], acc[mt][nt][3]);
            if (mode == 2) {
                const float2 x0 = *reinterpret_cast<const float2*>(
                    Xsub + ((size_t)b * NN + n) * CC + c);
                const float2 x1 = *reinterpret_cast<const float2*>(
                    Xsub + ((size_t)b * NN + n + 8) * CC + c);
                v0.x = fmaf(2.f, v0.x, -x0.x);
                v0.y = fmaf(2.f, v0.y, -x0.y);
                v1.x = fmaf(2.f, v1.x, -x1.x);
                v1.y = fmaf(2.f, v1.y, -x1.y);
            }
            *reinterpret_cast<float2*>(Y + ((size_t)b * NN + n) * CC + c) = v0;
            *reinterpret_cast<float2*>(Y + ((size_t)b * NN + n + 8) * CC + c) = v1;
        }
    }
}

// ---------------------------------------------------------------------------
// out3: per-node tensor-core contraction (tf32). One block (128 thr) per n.
//   D[64 b, 64 o] = XG[64 b, 192 kk] @ WT[64 o, 192 kk]^T  + bias
// ---------------------------------------------------------------------------
#define OSTR 196
#define OUT3_SMEM ((64 * OSTR * 2 + 64) * 4)
__global__ __launch_bounds__(128) void out3_kernel(const float* __restrict__ X,
                                                   const float* __restrict__ E,
                                                   const float* __restrict__ WTg,
                                                   const float* __restrict__ bp,
                                                   float* __restrict__ OUT) {
    extern __shared__ float sm[];
    float* XGs = sm;                  // 64 * 196
    float* WTs = sm + 64 * OSTR;      // 64 * 196
    float* bs = sm + 64 * OSTR * 2;   // 64
    __shared__ float en[EMBD];

    int n = blockIdx.x;
    int tid = threadIdx.x;
    int wid = tid >> 5;
    int lid = tid & 31;
    if (tid < EMBD) en[tid] = E[n * EMBD + tid];
    __syncthreads();

    const float* srcs[3] = {X, g_y1, g_y2};
#pragma unroll
    for (int k = 0; k < 3; k++) {
        const float* src = srcs[k];
#pragma unroll
        for (int rep = 0; rep < 32; rep++) {
            int idx = tid + rep * 128;
            int b = idx >> 6, i = idx & 63;
            XGs[b * OSTR + k * 64 + i] = tf32r(src[((size_t)b * NN + n) * CC + i]);
        }
    }
    {
        const float4* src = reinterpret_cast<const float4*>(WTg + (size_t)n * 12288);
#pragma unroll
        for (int rep = 0; rep < 24; rep++) {
            int f4 = tid + rep * 128;
            int idx = f4 * 4;
            int o = idx / 192, kk = idx - o * 192;
            *reinterpret_cast<float4*>(&WTs[o * OSTR + kk]) = src[f4];
        }
    }
    if (tid < 64) {
        float s = 0.f;
#pragma unroll
        for (int d = 0; d < EMBD; d++) s = fmaf(en[d], bp[d * 64 + tid], s);
        bs[tid] = s;
    }
    __syncthreads();

    int lm = lid >> 3, lrw = lid & 7;
    uint32_t aLane = smem_u32(XGs) + ((wid * 16 + (lm & 1) * 8 + lrw) * OSTR + (lm >> 1) * 4) * 4;
    uint32_t bLane = smem_u32(WTs) + (((lm >> 1) * 8 + lrw) * OSTR + (lm & 1) * 4) * 4;

    float acc[8][4];
#pragma unroll
    for (int nt = 0; nt < 8; nt++)
#pragma unroll
        for (int q = 0; q < 4; q++) acc[nt][q] = 0.f;

#pragma unroll 2
    for (int kt = 0; kt < 24; kt++) {
        int k0 = kt * 8;
        uint32_t af[4];
        ldsm4(af, aLane + k0 * 4);
#pragma unroll
        for (int g = 0; g < 4; g++) {
            uint32_t bf[4];
            ldsm4(bf, bLane + (g * 16 * OSTR + k0) * 4);
            mma8(acc[g * 2 + 0], af, &bf[0]);
            mma8(acc[g * 2 + 1], af, &bf[2]);
        }
    }

    int lr = lid >> 2, lc = lid & 3;
    int b0 = wid * 16 + lr;
#pragma unroll
    for (int nt = 0; nt < 8; nt++) {
        int o = nt * 8 + lc * 2;
        float2 bias = *reinterpret_cast<const float2*>(&bs[o]);
        float2 v0 = make_float2(acc[nt][0] + bias.x, acc[nt][1] + bias.y);
        float2 v1 = make_float2(acc[nt][2] + bias.x, acc[nt][3] + bias.y);
        *reinterpret_cast<float2*>(OUT + ((size_t)b0 * NN + n) * CC + o) = v0;
        *reinterpret_cast<float2*>(OUT + ((size_t)(b0 + 8) * NN + n) * CC + o) = v1;
    }
}

// ---------------------------------------------------------------------------
extern "C" void kernel_launch(void* const* d_in, const int* in_sizes, int n_in,
                              void* d_out, int out_size) {
    const float *x = nullptr, *E = nullptr, *wp = nullptr, *bp = nullptr;
    for (int i = 0; i < n_in; i++) {
        switch (in_sizes[i]) {
            case BB * NN * CC:       x = (const float*)d_in[i]; break;
            case NN * EMBD:          E = (const float*)d_in[i]; break;
            case EMBD * 3 * CC * CC: wp = (const float*)d_in[i]; break;
            case EMBD * CC:          bp = (const float*)d_in[i]; break;
        }
    }
    float* out = (float*)d_out;

    __half *A, *XT, *y1T;
    float *y1, *y2, *WT;
    cudaGetSymbolAddress((void**)&A, g_A);
    cudaGetSymbolAddress((void**)&XT, g_XT);
    cudaGetSymbolAddress((void**)&y1, g_y1);
    cudaGetSymbolAddress((void**)&y1T, g_y1T);
    cudaGetSymbolAddress((void**)&y2, g_y2);
    cudaGetSymbolAddress((void**)&WT, g_WT);

    supports_kernel<<<NN, 256>>>(E, A);
    trh_kernel<<<dim3(NN / 32, CC / 32, BB), 256>>>(x, XT);
    wpre_kernel<<<dim3(48, 64), 256>>>(E, wp, WT);

    cudaFuncSetAttribute(mma_gemm, cudaFuncAttributeMaxDynamicSharedMemorySize, GEMM_SMEM);
    dim3 ggrid(NN / 128, (BB * CC) / 128);
    mma_gemm<<<ggrid, 256, GEMM_SMEM>>>(A, XT, y1, nullptr, 1);
    trh_kernel<<<dim3(NN / 32, CC / 32, BB), 256>>>(y1, y1T);
    mma_gemm<<<ggrid, 256, GEMM_SMEM>>>(A, y1T, y2, x, 2);

    cudaFuncSetAttribute(out3_kernel, cudaFuncAttributeMaxDynamicSharedMemorySize, OUT3_SMEM);
    out3_kernel<<<NN, 128, OUT3_SMEM>>>(x, E, WT, bp, out);
}